// round 1
// baseline (speedup 1.0000x reference)
#include <cuda_runtime.h>
#include <math.h>

// Problem constants (fixed by the dataset)
#define B_   64
#define NPG  1024
#define C_   256
#define EC   48
#define N_   (B_*NPG)        // 65536 nodes
#define E_   (N_*16)         // 1048576 edges
#define K1   (NPG/2)         // 512 kept after layer 1
#define K2   (NPG/4)         // 256 kept after layer 2
#define ET   128             // edges per tile in edge kernel

// ---------------- scratch (static device arrays; no allocation) ----------------
__device__ float g_p[N_];        // x @ out_w
__device__ float g_a1[N_];       // x @ sc_w1
__device__ float g_a2[N_];       // x @ sc_w2
__device__ float g_t1[N_];       // tanh(score1)
__device__ float g_num1[N_];
__device__ float g_cnt1[N_];
__device__ float g_W2[E_];       // edge_attr @ dp_w2 + dp_b2
__device__ int   g_map[N_];      // orig node -> layer2 new id (or -1)
__device__ int   g_perm1[B_*K1]; // new id -> orig node
__device__ float g_num2[B_*K1];
__device__ float g_cnt2[B_*K1];
__device__ float g_S0[B_];       // per-graph sum of p

// float -> order-preserving unsigned (ascending)
__device__ __forceinline__ unsigned fkey(float f) {
    unsigned b = __float_as_uint(f);
    return (b & 0x80000000u) ? ~b : (b | 0x80000000u);
}

// descending bitonic sort of n (power of 2) u64 keys in shared memory
__device__ __forceinline__ void bitonic_desc(unsigned long long* key, int n, int tid, int nthreads) {
    for (int k = 2; k <= n; k <<= 1) {
        for (int j = k >> 1; j > 0; j >>= 1) {
            __syncthreads();
            for (int i = tid; i < n; i += nthreads) {
                int ixj = i ^ j;
                if (ixj > i) {
                    unsigned long long a = key[i], b = key[ixj];
                    bool up = ((i & k) == 0);
                    if (up ? (a < b) : (a > b)) { key[i] = b; key[ixj] = a; }
                }
            }
        }
    }
    __syncthreads();
}

// ---------------- kernels ----------------

__global__ void k_zero() {
    int i = blockIdx.x * 256 + threadIdx.x;     // grid covers N_
    g_num1[i] = 0.f; g_cnt1[i] = 0.f;
    if (i < B_ * K1) { g_num2[i] = 0.f; g_cnt2[i] = 0.f; }
}

// One pass over x: three dot products per row (warp per row, coalesced float4)
__global__ void k_x(const float* __restrict__ x, const float* __restrict__ scw1,
                    const float* __restrict__ scw2, const float* __restrict__ outw) {
    __shared__ float4 w4[3][C_ / 4];
    int tid = threadIdx.x;
    if (tid < 64)        w4[0][tid]       = ((const float4*)scw1)[tid];
    else if (tid < 128)  w4[1][tid - 64]  = ((const float4*)scw2)[tid - 64];
    else if (tid < 192)  w4[2][tid - 128] = ((const float4*)outw)[tid - 128];
    __syncthreads();

    int lane = tid & 31, warp = tid >> 5;
    int row = blockIdx.x * 8 + warp;
    const float4* xr = (const float4*)(x + (size_t)row * C_);
    float d0 = 0.f, d1 = 0.f, d2 = 0.f;
#pragma unroll
    for (int k = 0; k < 2; k++) {
        int c4 = k * 32 + lane;
        float4 v  = xr[c4];
        float4 wa = w4[0][c4], wb = w4[1][c4], wc = w4[2][c4];
        d0 += v.x * wa.x + v.y * wa.y + v.z * wa.z + v.w * wa.w;
        d1 += v.x * wb.x + v.y * wb.y + v.z * wb.z + v.w * wb.w;
        d2 += v.x * wc.x + v.y * wc.y + v.z * wc.z + v.w * wc.w;
    }
#pragma unroll
    for (int o = 16; o; o >>= 1) {
        d0 += __shfl_xor_sync(0xffffffffu, d0, o);
        d1 += __shfl_xor_sync(0xffffffffu, d1, o);
        d2 += __shfl_xor_sync(0xffffffffu, d2, o);
    }
    if (lane == 0) { g_a1[row] = d0; g_a2[row] = d1; g_p[row] = d2; }
}

// One pass over edge_attr: W1, W2 per edge + layer-1 message atomics.
// Tiles staged through shared (padded stride 49 -> conflict-free) so global
// loads are fully coalesced float4s.
__global__ void k_edge(const float* __restrict__ ea, const int* __restrict__ ei,
                       const float* __restrict__ dpw1, const float* __restrict__ dpb1,
                       const float* __restrict__ dpw2, const float* __restrict__ dpb2,
                       const float* __restrict__ scb1) {
    __shared__ float sh[ET][EC + 1];
    __shared__ float w1s[EC], w2s[EC];
    int tid = threadIdx.x;
    if (tid < EC) { w1s[tid] = dpw1[tid]; w2s[tid] = dpw2[tid]; }

    size_t e0 = (size_t)blockIdx.x * ET;
    const float4* ea4 = (const float4*)(ea + e0 * EC);
#pragma unroll
    for (int it = 0; it < (ET * EC / 4) / ET; it++) {   // 12 float4 per thread
        int f = it * ET + tid;
        float4 v = ea4[f];
        int row = f / (EC / 4), c = (f % (EC / 4)) * 4;
        sh[row][c] = v.x; sh[row][c + 1] = v.y; sh[row][c + 2] = v.z; sh[row][c + 3] = v.w;
    }
    __syncthreads();

    float w1 = dpb1[0], w2 = dpb2[0];
#pragma unroll
    for (int j = 0; j < EC; j++) {
        float f = sh[tid][j];
        w1 = fmaf(f, w1s[j], w1);
        w2 = fmaf(f, w2s[j], w2);
    }
    size_t e = e0 + tid;
    g_W2[e] = w2;
    int s = ei[e], d = ei[E_ + e];
    float msg = (g_a1[s] + scb1[0]) * w1;
    atomicAdd(&g_num1[d], msg);
    atomicAdd(&g_cnt1[d], 1.0f);
}

// Layer-1 scores, tanh, per-graph top-512 (exact jax tie-break), build node map,
// and per-graph sum of p.
__global__ void k_top1() {
    __shared__ unsigned long long key[NPG];
    __shared__ float red[512];
    int g = blockIdx.x, tid = threadIdx.x, base = g * NPG;

    for (int i = tid; i < NPG; i += 512) {
        float c = g_cnt1[base + i];
        float s = (c > 0.f) ? g_num1[base + i] / c : 0.f;
        g_t1[base + i] = tanhf(s);
        key[i] = ((unsigned long long)fkey(s) << 32) | (unsigned)(~i);
    }
    float ps = g_p[base + tid] + g_p[base + tid + 512];
    red[tid] = ps;
    for (int o = 256; o; o >>= 1) { __syncthreads(); if (tid < o) red[tid] += red[tid + o]; }
    if (tid == 0) g_S0[g] = red[0];

    bitonic_desc(key, NPG, tid, 512);

    for (int pos = tid; pos < NPG; pos += 512) {
        int idx = (int)(~(unsigned)key[pos]);      // recover local index
        if (pos < K1) {
            g_map[base + idx] = g * K1 + pos;       // new id = sorted rank (jax perm order)
            g_perm1[g * K1 + pos] = base + idx;
        } else {
            g_map[base + idx] = -1;
        }
    }
}

// Layer-2 message passing over surviving edges
__global__ void k_edge2(const int* __restrict__ ei, const float* __restrict__ scb2) {
    size_t e = (size_t)blockIdx.x * 256 + threadIdx.x;
    int s = ei[e], d = ei[E_ + e];
    int nd = g_map[d];
    if (nd >= 0 && g_map[s] >= 0) {
        float xs2 = fmaf(g_a2[s], g_t1[s], scb2[0]);   // (x*t1)@sc_w2 + sc_b2
        atomicAdd(&g_num2[nd], xs2 * g_W2[e]);
        atomicAdd(&g_cnt2[nd], 1.0f);
    }
}

// Layer-2 scores, top-256 of 512 per graph, final reduction + sigmoid
__global__ void k_top2(const float* __restrict__ outb, float* __restrict__ out) {
    __shared__ unsigned long long key[K1];
    __shared__ float c1[K1], c2[K1];
    __shared__ float red[256];
    int g = blockIdx.x, tid = threadIdx.x, base = g * K1;

    for (int i = tid; i < K1; i += 256) {
        float c = g_cnt2[base + i];
        float s = (c > 0.f) ? g_num2[base + i] / c : 0.f;
        int orig = g_perm1[base + i];
        float pc = g_p[orig] * g_t1[orig];
        c1[i] = pc;                 // layer-1 contribution p*t1
        c2[i] = pc * tanhf(s);      // layer-2 contribution p*t1*t2
        key[i] = ((unsigned long long)fkey(s) << 32) | (unsigned)(~i);
    }
    bitonic_desc(key, K1, tid, 256);

    // positions [0,256) are kept at layer 2; tid covers them exactly once
    int idx = (int)(~(unsigned)key[tid]);
    float acc = c2[idx] + c1[tid] + c1[tid + 256];   // S2 part + S1 part
    red[tid] = acc;
    for (int o = 128; o; o >>= 1) { __syncthreads(); if (tid < o) red[tid] += red[tid + o]; }
    if (tid == 0) {
        float tot = g_S0[g] + red[0] + outb[0];
        out[g] = 1.f / (1.f + expf(-tot));
    }
}

// ---------------- launch ----------------
extern "C" void kernel_launch(void* const* d_in, const int* in_sizes, int n_in,
                              void* d_out, int out_size) {
    const float* x    = (const float*)d_in[0];
    const int*   ei   = (const int*)  d_in[1];
    const float* ea   = (const float*)d_in[2];
    // d_in[3] = batch (implied by NPG, unused)
    const float* dpw1 = (const float*)d_in[4];
    const float* dpb1 = (const float*)d_in[5];
    const float* scw1 = (const float*)d_in[6];
    const float* scb1 = (const float*)d_in[7];
    const float* dpw2 = (const float*)d_in[8];
    const float* dpb2 = (const float*)d_in[9];
    const float* scw2 = (const float*)d_in[10];
    const float* scb2 = (const float*)d_in[11];
    const float* outw = (const float*)d_in[12];
    const float* outb = (const float*)d_in[13];
    float* out = (float*)d_out;

    k_zero <<<N_ / 256, 256>>>();
    k_x    <<<N_ / 8,   256>>>(x, scw1, scw2, outw);
    k_edge <<<E_ / ET,  ET >>>(ea, ei, dpw1, dpb1, dpw2, dpb2, scb1);
    k_top1 <<<B_,       512>>>();
    k_edge2<<<E_ / 256, 256>>>(ei, scb2);
    k_top2 <<<B_,       256>>>(outb, out);
}